// round 12
// baseline (speedup 1.0000x reference)
#include <cuda_runtime.h>
#include <cuda_fp16.h>
#include <cuda_fp8.h>
#include <cstdint>

// ---------------- Problem constants / scratch ----------------
#define MAXN 131072
#define MAXE 2000000
#define GRAPHS 128
#define DIM 64

__device__ int       g_is64;
__device__ int       g_indeg[MAXN];
__device__ float     g_dinv[MAXN];
__device__ int       g_rowptr[MAXN + 1];
__device__ int       g_cursor[MAXN];
__device__ long long g_look[192];
__device__ int       g_esrc[MAXE];          // edge = src only (4 B)
__device__ uint4     g_p8[MAXN * 4];        // fp8 payload p = dinv * xw
__device__ __half    g_x16[MAXN * DIM];     // fp16 copy of input features
__device__ __half    g_bufA[MAXN * DIM];    // fp16 hidden (single buffer, reused)
__device__ __half    g_W16[3 * DIM * DIM];

// ---------------- helpers ----------------
__device__ __forceinline__ int loadIdx(const void* p, long long i) {
    if (g_is64) return (int)((const long long*)p)[i];
    return ((const int*)p)[i];
}

__device__ __forceinline__ int detect64(const void* p, int n) {
    const long long* q = (const long long*)p;
    long long v = q[threadIdx.x & 31];
    unsigned ok = __ballot_sync(0xffffffffu, v >= 0 && v < (long long)n);
    return ok == 0xffffffffu;
}

// ---------------- prep (side stream): x fp32->fp16, W fp32->fp16 ----------------
__global__ void prep_kernel(const float* __restrict__ x, const float* __restrict__ W1,
                            const float* __restrict__ W2, const float* __restrict__ W3,
                            int n4) {
    int gid = blockIdx.x * blockDim.x + threadIdx.x;
    if (gid < 3072) {
        const float* Ws = (gid < 1024) ? W1 : (gid < 2048 ? W2 : W3);
        int j = gid & 1023;
        float4 v = ((const float4*)Ws)[j];
        __half2 p0 = __floats2half2_rn(v.x, v.y);
        __half2 p1 = __floats2half2_rn(v.z, v.w);
        uint2 u;
        u.x = *(unsigned*)&p0;
        u.y = *(unsigned*)&p1;
        *(uint2*)&g_W16[(gid >> 10) * 4096 + j * 4] = u;
    }
    for (int i = gid; i < n4; i += gridDim.x * blockDim.x) {
        float4 v = ((const float4*)x)[i];
        __half2 p0 = __floats2half2_rn(v.x, v.y);
        __half2 p1 = __floats2half2_rn(v.z, v.w);
        uint2 u;
        u.x = *(unsigned*)&p0;
        u.y = *(unsigned*)&p1;
        ((uint2*)g_x16)[i] = u;
    }
}

// ---------------- degree histogram (+dtype detect publish) ----------------
__global__ void deg_kernel(const void* eidx, int E, int n) {
    int is64 = detect64(eidx, n);
    if (blockIdx.x == 0 && threadIdx.x == 0) g_is64 = is64;
    int e = blockIdx.x * blockDim.x + threadIdx.x;
    if (e >= E) return;
    int d = is64 ? (int)((const long long*)eidx)[(long long)E + e]
                 : ((const int*)eidx)[E + e];
    atomicAdd(&g_indeg[d], 1);
}

// ---------------- single-kernel scan with decoupled lookback ----------------
__global__ void scan_kernel(int n, int E) {
    __shared__ int sh[256];
    __shared__ int s_off;
    int bid = blockIdx.x, tid = threadIdx.x;
    int base = bid * 1024 + tid * 4;
    int v[4];
#pragma unroll
    for (int i = 0; i < 4; i++) {
        int idx = base + i;
        v[i] = (idx < n) ? g_indeg[idx] : 0;
        if (idx < n) {
            g_dinv[idx] = rsqrtf((float)(v[i] + 1));  // +1 self-loop
            g_indeg[idx] = 0;                          // re-arm for next launch
        }
    }
    int tsum = v[0] + v[1] + v[2] + v[3];
    sh[tid] = tsum;
    __syncthreads();
    int val = tsum;
    for (int off = 1; off < 256; off <<= 1) {
        int t = (tid >= off) ? sh[tid - off] : 0;
        __syncthreads();
        val += t;
        sh[tid] = val;
        __syncthreads();
    }
    if (tid == 255)
        ((volatile long long*)g_look)[bid] = 0x100000000LL | (unsigned)val;
    int myExcl = val - tsum;
    if (tid < 32) {
        int off = 0;
        for (int j = tid; j < bid; j += 32) {
            long long lv;
            do { lv = ((volatile long long*)g_look)[j]; } while (lv == 0);
            off += (int)(lv & 0xffffffffLL);
        }
#pragma unroll
        for (int s = 16; s > 0; s >>= 1) off += __shfl_down_sync(0xffffffffu, off, s);
        if (tid == 0) s_off = off;
    }
    __syncthreads();
    int run = myExcl + s_off;
#pragma unroll
    for (int i = 0; i < 4; i++) {
        int idx = base + i;
        if (idx < n) {
            g_rowptr[idx] = run;
            g_cursor[idx] = run;
        }
        run += v[i];
    }
    if (bid == 0 && tid == 0) g_rowptr[n] = E;
}

// ---------------- edge scatter into CSR: src index only ----------------
__global__ void scatter_kernel(const void* eidx, int E, int n) {
    if (blockIdx.x == 0 && threadIdx.x < 192) g_look[threadIdx.x] = 0;
    int is64 = detect64(eidx, n);
    int e = blockIdx.x * blockDim.x + threadIdx.x;
    if (e >= E) return;
    int s, d;
    if (is64) {
        s = (int)((const long long*)eidx)[e];
        d = (int)((const long long*)eidx)[(long long)E + e];
    } else {
        s = ((const int*)eidx)[e];
        d = ((const int*)eidx)[E + e];
    }
    int pos = atomicAdd(&g_cursor[d], 1);
    g_esrc[pos] = s;
}

// ---------------- tensor-core GEMM: P[n,64](fp8) = dinv[row] * (X[n,64] @ W) ----------------
__global__ __launch_bounds__(256) void gemm_mma_kernel(
    const __half* __restrict__ X, const __half* __restrict__ Wg,
    uint4* __restrict__ P, int n) {
    __shared__ __half Wh[64 * 72];
    __shared__ __half Xsh[64 * 72];
    __shared__ float dsh[64];
    __shared__ __align__(16) uint8_t Ysh[64 * 64];
    int tid = threadIdx.x;
    int warp = tid >> 5, lane = tid & 31;
    int nb = blockIdx.x * 64;

    // 1) cp.async prefetch X rows
#pragma unroll
    for (int i = 0; i < 4; i++) {
        int idx = i * 256 + tid;           // 0..1023
        int row = idx >> 4, seg = idx & 15;
        __half* dst = &Xsh[row * 72 + seg * 4];
        if (nb + row < n) {
            const __half* src = X + (size_t)(nb + row) * 64 + seg * 4;
            uint32_t sdst = (uint32_t)__cvta_generic_to_shared(dst);
            asm volatile("cp.async.ca.shared.global [%0], [%1], 8;" :: "r"(sdst), "l"(src));
        } else {
            *(uint2*)dst = make_uint2(0, 0);
        }
    }
    asm volatile("cp.async.commit_group;");

    // 2) W fp16 -> smem (k-major, stride 72)
    for (int i = tid; i < 512; i += 256) {
        uint4 u = ((const uint4*)Wg)[i];  // 8 halfs
        int k = i >> 3, c = (i & 7) * 8;
        *(uint4*)&Wh[k * 72 + c] = u;
    }
    if (tid < 64) dsh[tid] = (nb + tid < n) ? g_dinv[nb + tid] : 0.f;

    asm volatile("cp.async.wait_group 0;");
    __syncthreads();

    int rt = warp >> 1;
    int ch = warp & 1;
    int r0 = rt * 16;
    float D[4][4];
#pragma unroll
    for (int nc = 0; nc < 4; nc++)
#pragma unroll
        for (int j = 0; j < 4; j++) D[nc][j] = 0.f;

#pragma unroll
    for (int kc = 0; kc < 4; kc++) {
        uint32_t A[4];
        {
            const __half* ap = &Xsh[(r0 + (lane & 15)) * 72 + kc * 16 + (lane >> 4) * 8];
            uint32_t sa = (uint32_t)__cvta_generic_to_shared(ap);
            asm volatile("ldmatrix.sync.aligned.m8n8.x4.shared.b16 {%0,%1,%2,%3}, [%4];"
                         : "=r"(A[0]), "=r"(A[1]), "=r"(A[2]), "=r"(A[3]) : "r"(sa));
        }
        uint32_t B[4][2];
#pragma unroll
        for (int np = 0; np < 2; np++) {
            int krow = kc * 16 + (lane & 15);
            int ncol = ch * 32 + np * 16 + (lane >> 4) * 8;
            const __half* bp = &Wh[krow * 72 + ncol];
            uint32_t sb = (uint32_t)__cvta_generic_to_shared(bp);
            asm volatile("ldmatrix.sync.aligned.m8n8.x4.trans.shared.b16 {%0,%1,%2,%3}, [%4];"
                         : "=r"(B[np * 2][0]), "=r"(B[np * 2][1]),
                           "=r"(B[np * 2 + 1][0]), "=r"(B[np * 2 + 1][1])
                         : "r"(sb));
        }
#pragma unroll
        for (int nc = 0; nc < 4; nc++) {
            asm volatile(
                "mma.sync.aligned.m16n8k16.row.col.f32.f16.f16.f32 "
                "{%0,%1,%2,%3}, {%4,%5,%6,%7}, {%8,%9}, {%0,%1,%2,%3};"
                : "+f"(D[nc][0]), "+f"(D[nc][1]), "+f"(D[nc][2]), "+f"(D[nc][3])
                : "r"(A[0]), "r"(A[1]), "r"(A[2]), "r"(A[3]),
                  "r"(B[nc][0]), "r"(B[nc][1]));
        }
    }
    int g = lane >> 2;
    int cb = 2 * (lane & 3);
    float dlo = dsh[r0 + g];
    float dhi = dsh[r0 + g + 8];
#pragma unroll
    for (int nc = 0; nc < 4; nc++) {
        int c0 = ch * 32 + nc * 8 + cb;
        float2 lo = make_float2(D[nc][0] * dlo, D[nc][1] * dlo);
        float2 hi = make_float2(D[nc][2] * dhi, D[nc][3] * dhi);
        unsigned short p0 = __nv_cvt_float2_to_fp8x2(lo, __NV_SATFINITE, __NV_E4M3);
        unsigned short p1 = __nv_cvt_float2_to_fp8x2(hi, __NV_SATFINITE, __NV_E4M3);
        *(unsigned short*)&Ysh[(r0 + g) * 64 + c0] = p0;
        *(unsigned short*)&Ysh[(r0 + g + 8) * 64 + c0] = p1;
    }
    __syncthreads();
    {
        int row = tid >> 2, q = tid & 3;
        int node = nb + row;
        if (node < n)
            P[(size_t)node * 4 + q] = ((const uint4*)Ysh)[row * 4 + q];
    }
}

// ---------------- aggregation: out = dinv[dst]*(sum p[src] + p[self]) + b ----------------
// 16 lanes x 4 B per row (R9 layout), with fully parallel predicated remainder.
__device__ __forceinline__ float4 fp8quad(const uint8_t* base, int node, int li) {
    uint32_t u = *(const uint32_t*)(base + (size_t)node * 64 + li * 4);
    __half2_raw h0 = __nv_cvt_fp8x2_to_halfraw2((unsigned short)(u & 0xffff), __NV_E4M3);
    __half2_raw h1 = __nv_cvt_fp8x2_to_halfraw2((unsigned short)(u >> 16), __NV_E4M3);
    float2 a = __half22float2(*(__half2*)&h0);
    float2 b = __half22float2(*(__half2*)&h1);
    return make_float4(a.x, a.y, b.x, b.y);
}

__global__ void aggregate_kernel(const uint8_t* __restrict__ p8, __half* __restrict__ out,
                                 const float* __restrict__ bias, int relu, int n) {
    int node = (blockIdx.x * blockDim.x + threadIdx.x) >> 5;
    int lane = threadIdx.x & 31;
    if (node >= n) return;
    int start = g_rowptr[node];
    int end = g_rowptr[node + 1];
    float dv = g_dinv[node];
    int li = lane & 15;
    int half_ = lane >> 4;
    float4 acc = make_float4(0.f, 0.f, 0.f, 0.f);
    if (half_ == 0) acc = fp8quad(p8, node, li);  // self contribution once
    int e = start + half_;
    // full 16-edge pipelined iterations (8 slots x 2 half-warps)
    for (; e + 14 < end; e += 16) {
        int s[8];
#pragma unroll
        for (int i = 0; i < 8; i++) s[i] = g_esrc[e + 2 * i];
        float4 v[8];
#pragma unroll
        for (int i = 0; i < 8; i++) v[i] = fp8quad(p8, s[i], li);
#pragma unroll
        for (int i = 0; i < 8; i++) {
            acc.x += v[i].x; acc.y += v[i].y;
            acc.z += v[i].z; acc.w += v[i].w;
        }
    }
    // remainder (<16 edges): one fully parallel predicated pass
    if (e < end) {
        float4 v[8];
#pragma unroll
        for (int i = 0; i < 8; i++) {
            int idx = e + 2 * i;
            if (idx < end) v[i] = fp8quad(p8, g_esrc[idx], li);
            else v[i] = make_float4(0.f, 0.f, 0.f, 0.f);
        }
#pragma unroll
        for (int i = 0; i < 8; i++) {
            acc.x += v[i].x; acc.y += v[i].y;
            acc.z += v[i].z; acc.w += v[i].w;
        }
    }
    // combine halves -> lanes 0..15 hold dims [4*li, 4*li+4)
    acc.x += __shfl_down_sync(0xffffffffu, acc.x, 16);
    acc.y += __shfl_down_sync(0xffffffffu, acc.y, 16);
    acc.z += __shfl_down_sync(0xffffffffu, acc.z, 16);
    acc.w += __shfl_down_sync(0xffffffffu, acc.w, 16);
    if (lane < 16) {
        float4 b4 = *(const float4*)(bias + li * 4);
        float o0 = dv * acc.x + b4.x;
        float o1 = dv * acc.y + b4.y;
        float o2 = dv * acc.z + b4.z;
        float o3 = dv * acc.w + b4.w;
        if (relu) {
            o0 = fmaxf(o0, 0.f); o1 = fmaxf(o1, 0.f);
            o2 = fmaxf(o2, 0.f); o3 = fmaxf(o3, 0.f);
        }
        __half2 p0 = __floats2half2_rn(o0, o1);
        __half2 p1 = __floats2half2_rn(o2, o3);
        uint2 u;
        u.x = *(unsigned*)&p0;
        u.y = *(unsigned*)&p1;
        ((uint2*)out)[(size_t)node * 16 + li] = u;
    }
}

// ---------------- fused pool + linear (batch sorted -> contiguous ranges) ----------------
__device__ __forceinline__ int lower_bound_batch(const void* batch, int n, int key) {
    int lo = 0, hi = n;
    while (lo < hi) {
        int mid = (lo + hi) >> 1;
        if (loadIdx(batch, mid) < key) lo = mid + 1;
        else hi = mid;
    }
    return lo;
}

__global__ void poolfinal_kernel(const __half* __restrict__ h, const void* batch,
                                 const float* __restrict__ Wlin, const float* __restrict__ blin,
                                 float* __restrict__ out, int n) {
    int g = blockIdx.x;
    int tid = threadIdx.x;  // 256
    __shared__ int s_lo, s_hi;
    if (tid == 0) s_lo = lower_bound_batch(batch, n, g);
    if (tid == 1) s_hi = lower_bound_batch(batch, n, g + 1);
    __syncthreads();
    int lo = s_lo, hi = s_hi;
    int dim = tid & 63;
    int sub = tid >> 6;
    float acc = 0.f;
    for (int node = lo + sub; node < hi; node += 4)
        acc += __half2float(h[(size_t)node * 64 + dim]);
    __shared__ float red[256];
    __shared__ float mean[64];
    red[tid] = acc;
    __syncthreads();
    if (tid < 64) {
        float s = red[tid] + red[tid + 64] + red[tid + 128] + red[tid + 192];
        float cnt = (float)(hi - lo);
        mean[tid] = s / fmaxf(cnt, 1.0f);
    }
    __syncthreads();
    if (tid < 64) {
        float a = blin[tid];
#pragma unroll
        for (int k = 0; k < 64; k++) a += mean[k] * Wlin[k * 64 + tid];
        out[g * 64 + tid] = a;
    }
}

// ---------------- launch ----------------
extern "C" void kernel_launch(void* const* d_in, const int* in_sizes, int n_in,
                              void* d_out, int out_size) {
    const float* x     = (const float*)d_in[0];
    const void*  eidx  = d_in[1];
    const void*  batch = d_in[2];
    const float* W1 = (const float*)d_in[3];
    const float* b1 = (const float*)d_in[4];
    const float* W2 = (const float*)d_in[5];
    const float* b2 = (const float*)d_in[6];
    const float* W3 = (const float*)d_in[7];
    const float* b3 = (const float*)d_in[8];
    const float* Wlin = (const float*)d_in[9];
    const float* blin = (const float*)d_in[10];
    float* out = (float*)d_out;

    int N = in_sizes[0] / DIM;
    int E = in_sizes[1] / 2;

    uint4* p8;
    __half *bufA, *x16, *W16;
    cudaGetSymbolAddress((void**)&p8, g_p8);
    cudaGetSymbolAddress((void**)&bufA, g_bufA);
    cudaGetSymbolAddress((void**)&x16, g_x16);
    cudaGetSymbolAddress((void**)&W16, g_W16);
    const uint8_t* p8b = (const uint8_t*)p8;

    static cudaStream_t s2 = nullptr;
    static cudaEvent_t evFork = nullptr, evScan = nullptr, evJoin = nullptr;
    if (!s2) {
        cudaStreamCreateWithFlags(&s2, cudaStreamNonBlocking);
        cudaEventCreateWithFlags(&evFork, cudaEventDisableTiming);
        cudaEventCreateWithFlags(&evScan, cudaEventDisableTiming);
        cudaEventCreateWithFlags(&evJoin, cudaEventDisableTiming);
    }

    int nbScan = (N + 1023) / 1024;
    int gemmBlocks = (N + 63) / 64;
    int aggBlocks = (N * 32 + 255) / 256;

    // side stream: prep, then gemm1 once dinv is ready
    cudaEventRecord(evFork, 0);
    cudaStreamWaitEvent(s2, evFork, 0);
    prep_kernel<<<(N * 16 + 255) / 256, 256, 0, s2>>>(x, W1, W2, W3, N * 16);

    // main: edge setup chain
    deg_kernel<<<(E + 255) / 256, 256>>>(eidx, E, N);
    scan_kernel<<<nbScan, 256>>>(N, E);
    cudaEventRecord(evScan, 0);

    // gemm1 overlaps scatter
    cudaStreamWaitEvent(s2, evScan, 0);
    gemm_mma_kernel<<<gemmBlocks, 256, 0, s2>>>(x16, W16, p8, N);
    cudaEventRecord(evJoin, s2);

    scatter_kernel<<<(E + 255) / 256, 256>>>(eidx, E, N);
    cudaStreamWaitEvent(0, evJoin, 0);

    // layers
    aggregate_kernel<<<aggBlocks, 256>>>(p8b, bufA, b1, 1, N);
    gemm_mma_kernel<<<gemmBlocks, 256>>>(bufA, W16 + 4096, p8, N);
    aggregate_kernel<<<aggBlocks, 256>>>(p8b, bufA, b2, 1, N);
    gemm_mma_kernel<<<gemmBlocks, 256>>>(bufA, W16 + 8192, p8, N);
    aggregate_kernel<<<aggBlocks, 256>>>(p8b, bufA, b3, 0, N);

    poolfinal_kernel<<<GRAPHS, 256>>>(bufA, batch, Wlin, blin, out, N);
}

// round 13
// speedup vs baseline: 1.0455x; 1.0455x over previous
#include <cuda_runtime.h>
#include <cuda_fp16.h>
#include <cuda_fp8.h>
#include <cstdint>

// ---------------- Problem constants / scratch ----------------
#define MAXN 131072
#define MAXE 2000000
#define GRAPHS 128
#define DIM 64

__device__ int       g_is64;
__device__ int       g_indeg[MAXN];
__device__ float     g_dinv[MAXN];
__device__ int       g_rowptr[MAXN + 1];
__device__ int       g_cursor[MAXN];
__device__ long long g_look[192];
__device__ int       g_esrc[MAXE];          // edge = src only (4 B)
__device__ uint4     g_p8[MAXN * 4];        // fp8 payload p = dinv * xw
__device__ __half    g_x16[MAXN * DIM];     // fp16 copy of input features
__device__ __half    g_bufA[MAXN * DIM];    // fp16 hidden (single buffer, reused)
__device__ __half    g_W16[3 * DIM * DIM];

// ---------------- helpers ----------------
__device__ __forceinline__ int loadIdx(const void* p, long long i) {
    if (g_is64) return (int)((const long long*)p)[i];
    return ((const int*)p)[i];
}

__device__ __forceinline__ int detect64(const void* p, int n) {
    const long long* q = (const long long*)p;
    long long v = q[threadIdx.x & 31];
    unsigned ok = __ballot_sync(0xffffffffu, v >= 0 && v < (long long)n);
    return ok == 0xffffffffu;
}

// ---------------- prep (side stream): x fp32->fp16, W fp32->fp16 ----------------
__global__ void prep_kernel(const float* __restrict__ x, const float* __restrict__ W1,
                            const float* __restrict__ W2, const float* __restrict__ W3,
                            int n4) {
    int gid = blockIdx.x * blockDim.x + threadIdx.x;
    if (gid < 3072) {
        const float* Ws = (gid < 1024) ? W1 : (gid < 2048 ? W2 : W3);
        int j = gid & 1023;
        float4 v = ((const float4*)Ws)[j];
        __half2 p0 = __floats2half2_rn(v.x, v.y);
        __half2 p1 = __floats2half2_rn(v.z, v.w);
        uint2 u;
        u.x = *(unsigned*)&p0;
        u.y = *(unsigned*)&p1;
        *(uint2*)&g_W16[(gid >> 10) * 4096 + j * 4] = u;
    }
    for (int i = gid; i < n4; i += gridDim.x * blockDim.x) {
        float4 v = ((const float4*)x)[i];
        __half2 p0 = __floats2half2_rn(v.x, v.y);
        __half2 p1 = __floats2half2_rn(v.z, v.w);
        uint2 u;
        u.x = *(unsigned*)&p0;
        u.y = *(unsigned*)&p1;
        ((uint2*)g_x16)[i] = u;
    }
}

// ---------------- degree histogram (+dtype detect publish) ----------------
__global__ void deg_kernel(const void* eidx, int E, int n) {
    int is64 = detect64(eidx, n);
    if (blockIdx.x == 0 && threadIdx.x == 0) g_is64 = is64;
    int e = blockIdx.x * blockDim.x + threadIdx.x;
    if (e >= E) return;
    int d = is64 ? (int)((const long long*)eidx)[(long long)E + e]
                 : ((const int*)eidx)[E + e];
    atomicAdd(&g_indeg[d], 1);
}

// ---------------- single-kernel scan with decoupled lookback ----------------
__global__ void scan_kernel(int n, int E) {
    __shared__ int sh[256];
    __shared__ int s_off;
    int bid = blockIdx.x, tid = threadIdx.x;
    int base = bid * 1024 + tid * 4;
    int v[4];
#pragma unroll
    for (int i = 0; i < 4; i++) {
        int idx = base + i;
        v[i] = (idx < n) ? g_indeg[idx] : 0;
        if (idx < n) {
            g_dinv[idx] = rsqrtf((float)(v[i] + 1));  // +1 self-loop
            g_indeg[idx] = 0;                          // re-arm for next launch
        }
    }
    int tsum = v[0] + v[1] + v[2] + v[3];
    sh[tid] = tsum;
    __syncthreads();
    int val = tsum;
    for (int off = 1; off < 256; off <<= 1) {
        int t = (tid >= off) ? sh[tid - off] : 0;
        __syncthreads();
        val += t;
        sh[tid] = val;
        __syncthreads();
    }
    if (tid == 255)
        ((volatile long long*)g_look)[bid] = 0x100000000LL | (unsigned)val;
    int myExcl = val - tsum;
    if (tid < 32) {
        int off = 0;
        for (int j = tid; j < bid; j += 32) {
            long long lv;
            do { lv = ((volatile long long*)g_look)[j]; } while (lv == 0);
            off += (int)(lv & 0xffffffffLL);
        }
#pragma unroll
        for (int s = 16; s > 0; s >>= 1) off += __shfl_down_sync(0xffffffffu, off, s);
        if (tid == 0) s_off = off;
    }
    __syncthreads();
    int run = myExcl + s_off;
#pragma unroll
    for (int i = 0; i < 4; i++) {
        int idx = base + i;
        if (idx < n) {
            g_rowptr[idx] = run;
            g_cursor[idx] = run;
        }
        run += v[i];
    }
    if (bid == 0 && tid == 0) g_rowptr[n] = E;
}

// ---------------- edge scatter into CSR: src index only ----------------
__global__ void scatter_kernel(const void* eidx, int E, int n) {
    if (blockIdx.x == 0 && threadIdx.x < 192) g_look[threadIdx.x] = 0;
    int is64 = detect64(eidx, n);
    int e = blockIdx.x * blockDim.x + threadIdx.x;
    if (e >= E) return;
    int s, d;
    if (is64) {
        s = (int)((const long long*)eidx)[e];
        d = (int)((const long long*)eidx)[(long long)E + e];
    } else {
        s = ((const int*)eidx)[e];
        d = ((const int*)eidx)[E + e];
    }
    int pos = atomicAdd(&g_cursor[d], 1);
    g_esrc[pos] = s;
}

// ---------------- tensor-core GEMM: P[n,64](fp8) = dinv[row] * (X[n,64] @ W) ----------------
__global__ __launch_bounds__(256) void gemm_mma_kernel(
    const __half* __restrict__ X, const __half* __restrict__ Wg,
    uint4* __restrict__ P, int n) {
    __shared__ __half Wh[64 * 72];
    __shared__ __half Xsh[64 * 72];
    __shared__ float dsh[64];
    __shared__ __align__(16) uint8_t Ysh[64 * 64];
    int tid = threadIdx.x;
    int warp = tid >> 5, lane = tid & 31;
    int nb = blockIdx.x * 64;

    // 1) cp.async prefetch X rows
#pragma unroll
    for (int i = 0; i < 4; i++) {
        int idx = i * 256 + tid;           // 0..1023
        int row = idx >> 4, seg = idx & 15;
        __half* dst = &Xsh[row * 72 + seg * 4];
        if (nb + row < n) {
            const __half* src = X + (size_t)(nb + row) * 64 + seg * 4;
            uint32_t sdst = (uint32_t)__cvta_generic_to_shared(dst);
            asm volatile("cp.async.ca.shared.global [%0], [%1], 8;" :: "r"(sdst), "l"(src));
        } else {
            *(uint2*)dst = make_uint2(0, 0);
        }
    }
    asm volatile("cp.async.commit_group;");

    // 2) W fp16 -> smem (k-major, stride 72)
    for (int i = tid; i < 512; i += 256) {
        uint4 u = ((const uint4*)Wg)[i];  // 8 halfs
        int k = i >> 3, c = (i & 7) * 8;
        *(uint4*)&Wh[k * 72 + c] = u;
    }
    if (tid < 64) dsh[tid] = (nb + tid < n) ? g_dinv[nb + tid] : 0.f;

    asm volatile("cp.async.wait_group 0;");
    __syncthreads();

    int rt = warp >> 1;
    int ch = warp & 1;
    int r0 = rt * 16;
    float D[4][4];
#pragma unroll
    for (int nc = 0; nc < 4; nc++)
#pragma unroll
        for (int j = 0; j < 4; j++) D[nc][j] = 0.f;

#pragma unroll
    for (int kc = 0; kc < 4; kc++) {
        uint32_t A[4];
        {
            const __half* ap = &Xsh[(r0 + (lane & 15)) * 72 + kc * 16 + (lane >> 4) * 8];
            uint32_t sa = (uint32_t)__cvta_generic_to_shared(ap);
            asm volatile("ldmatrix.sync.aligned.m8n8.x4.shared.b16 {%0,%1,%2,%3}, [%4];"
                         : "=r"(A[0]), "=r"(A[1]), "=r"(A[2]), "=r"(A[3]) : "r"(sa));
        }
        uint32_t B[4][2];
#pragma unroll
        for (int np = 0; np < 2; np++) {
            int krow = kc * 16 + (lane & 15);
            int ncol = ch * 32 + np * 16 + (lane >> 4) * 8;
            const __half* bp = &Wh[krow * 72 + ncol];
            uint32_t sb = (uint32_t)__cvta_generic_to_shared(bp);
            asm volatile("ldmatrix.sync.aligned.m8n8.x4.trans.shared.b16 {%0,%1,%2,%3}, [%4];"
                         : "=r"(B[np * 2][0]), "=r"(B[np * 2][1]),
                           "=r"(B[np * 2 + 1][0]), "=r"(B[np * 2 + 1][1])
                         : "r"(sb));
        }
#pragma unroll
        for (int nc = 0; nc < 4; nc++) {
            asm volatile(
                "mma.sync.aligned.m16n8k16.row.col.f32.f16.f16.f32 "
                "{%0,%1,%2,%3}, {%4,%5,%6,%7}, {%8,%9}, {%0,%1,%2,%3};"
                : "+f"(D[nc][0]), "+f"(D[nc][1]), "+f"(D[nc][2]), "+f"(D[nc][3])
                : "r"(A[0]), "r"(A[1]), "r"(A[2]), "r"(A[3]),
                  "r"(B[nc][0]), "r"(B[nc][1]));
        }
    }
    int g = lane >> 2;
    int cb = 2 * (lane & 3);
    float dlo = dsh[r0 + g];
    float dhi = dsh[r0 + g + 8];
#pragma unroll
    for (int nc = 0; nc < 4; nc++) {
        int c0 = ch * 32 + nc * 8 + cb;
        float2 lo = make_float2(D[nc][0] * dlo, D[nc][1] * dlo);
        float2 hi = make_float2(D[nc][2] * dhi, D[nc][3] * dhi);
        unsigned short p0 = __nv_cvt_float2_to_fp8x2(lo, __NV_SATFINITE, __NV_E4M3);
        unsigned short p1 = __nv_cvt_float2_to_fp8x2(hi, __NV_SATFINITE, __NV_E4M3);
        *(unsigned short*)&Ysh[(r0 + g) * 64 + c0] = p0;
        *(unsigned short*)&Ysh[(r0 + g + 8) * 64 + c0] = p1;
    }
    __syncthreads();
    {
        int row = tid >> 2, q = tid & 3;
        int node = nb + row;
        if (node < n)
            P[(size_t)node * 4 + q] = ((const uint4*)Ysh)[row * 4 + q];
    }
}

// ---------------- aggregation: out = dinv[dst]*(sum p[src] + p[self]) + b ----------------
// 16 lanes x 4 B per row (R9 layout); remainder = parallel raw-u32 predicated pass
// (fp8 bit pattern 0x00 == 0.0f, so masked-off slots accumulate exact zeros).
__device__ __forceinline__ float4 fp8quad(const uint8_t* base, int node, int li) {
    uint32_t u = *(const uint32_t*)(base + (size_t)node * 64 + li * 4);
    __half2_raw h0 = __nv_cvt_fp8x2_to_halfraw2((unsigned short)(u & 0xffff), __NV_E4M3);
    __half2_raw h1 = __nv_cvt_fp8x2_to_halfraw2((unsigned short)(u >> 16), __NV_E4M3);
    float2 a = __half22float2(*(__half2*)&h0);
    float2 b = __half22float2(*(__half2*)&h1);
    return make_float4(a.x, a.y, b.x, b.y);
}

__device__ __forceinline__ void fp8quad_acc(uint32_t u, float4& acc) {
    __half2_raw h0 = __nv_cvt_fp8x2_to_halfraw2((unsigned short)(u & 0xffff), __NV_E4M3);
    __half2_raw h1 = __nv_cvt_fp8x2_to_halfraw2((unsigned short)(u >> 16), __NV_E4M3);
    float2 a = __half22float2(*(__half2*)&h0);
    float2 b = __half22float2(*(__half2*)&h1);
    acc.x += a.x; acc.y += a.y; acc.z += b.x; acc.w += b.y;
}

__global__ void aggregate_kernel(const uint8_t* __restrict__ p8, __half* __restrict__ out,
                                 const float* __restrict__ bias, int relu, int n) {
    int node = (blockIdx.x * blockDim.x + threadIdx.x) >> 5;
    int lane = threadIdx.x & 31;
    if (node >= n) return;
    int start = g_rowptr[node];
    int end = g_rowptr[node + 1];
    float dv = g_dinv[node];
    int li = lane & 15;
    int half_ = lane >> 4;
    float4 acc = make_float4(0.f, 0.f, 0.f, 0.f);
    if (half_ == 0) acc = fp8quad(p8, node, li);  // self contribution once
    int e = start + half_;
    // full 16-edge pipelined iterations (8 slots x 2 half-warps)
    for (; e + 14 < end; e += 16) {
        int s[8];
#pragma unroll
        for (int i = 0; i < 8; i++) s[i] = g_esrc[e + 2 * i];
        float4 v[8];
#pragma unroll
        for (int i = 0; i < 8; i++) v[i] = fp8quad(p8, s[i], li);
#pragma unroll
        for (int i = 0; i < 8; i++) {
            acc.x += v[i].x; acc.y += v[i].y;
            acc.z += v[i].z; acc.w += v[i].w;
        }
    }
    // remainder (<16 edges): parallel predicated pass on raw u32 (8 regs only)
    if (e < end) {
        uint32_t u[8];
#pragma unroll
        for (int i = 0; i < 8; i++) {
            int idx = e + 2 * i;
            u[i] = (idx < end)
                 ? *(const uint32_t*)(p8 + (size_t)g_esrc[idx] * 64 + li * 4)
                 : 0u;
        }
#pragma unroll
        for (int i = 0; i < 8; i++) fp8quad_acc(u[i], acc);
    }
    // combine halves -> lanes 0..15 hold dims [4*li, 4*li+4)
    acc.x += __shfl_down_sync(0xffffffffu, acc.x, 16);
    acc.y += __shfl_down_sync(0xffffffffu, acc.y, 16);
    acc.z += __shfl_down_sync(0xffffffffu, acc.z, 16);
    acc.w += __shfl_down_sync(0xffffffffu, acc.w, 16);
    if (lane < 16) {
        float4 b4 = *(const float4*)(bias + li * 4);
        float o0 = dv * acc.x + b4.x;
        float o1 = dv * acc.y + b4.y;
        float o2 = dv * acc.z + b4.z;
        float o3 = dv * acc.w + b4.w;
        if (relu) {
            o0 = fmaxf(o0, 0.f); o1 = fmaxf(o1, 0.f);
            o2 = fmaxf(o2, 0.f); o3 = fmaxf(o3, 0.f);
        }
        __half2 p0 = __floats2half2_rn(o0, o1);
        __half2 p1 = __floats2half2_rn(o2, o3);
        uint2 u;
        u.x = *(unsigned*)&p0;
        u.y = *(unsigned*)&p1;
        ((uint2*)out)[(size_t)node * 16 + li] = u;
    }
}

// ---------------- fused pool + linear (batch sorted -> contiguous ranges) ----------------
__device__ __forceinline__ int lower_bound_batch(const void* batch, int n, int key) {
    int lo = 0, hi = n;
    while (lo < hi) {
        int mid = (lo + hi) >> 1;
        if (loadIdx(batch, mid) < key) lo = mid + 1;
        else hi = mid;
    }
    return lo;
}

__global__ void poolfinal_kernel(const __half* __restrict__ h, const void* batch,
                                 const float* __restrict__ Wlin, const float* __restrict__ blin,
                                 float* __restrict__ out, int n) {
    int g = blockIdx.x;
    int tid = threadIdx.x;  // 256
    __shared__ int s_lo, s_hi;
    if (tid == 0) s_lo = lower_bound_batch(batch, n, g);
    if (tid == 1) s_hi = lower_bound_batch(batch, n, g + 1);
    __syncthreads();
    int lo = s_lo, hi = s_hi;
    int dim = tid & 63;
    int sub = tid >> 6;
    float acc = 0.f;
    for (int node = lo + sub; node < hi; node += 4)
        acc += __half2float(h[(size_t)node * 64 + dim]);
    __shared__ float red[256];
    __shared__ float mean[64];
    red[tid] = acc;
    __syncthreads();
    if (tid < 64) {
        float s = red[tid] + red[tid + 64] + red[tid + 128] + red[tid + 192];
        float cnt = (float)(hi - lo);
        mean[tid] = s / fmaxf(cnt, 1.0f);
    }
    __syncthreads();
    if (tid < 64) {
        float a = blin[tid];
#pragma unroll
        for (int k = 0; k < 64; k++) a += mean[k] * Wlin[k * 64 + tid];
        out[g * 64 + tid] = a;
    }
}

// ---------------- launch ----------------
extern "C" void kernel_launch(void* const* d_in, const int* in_sizes, int n_in,
                              void* d_out, int out_size) {
    const float* x     = (const float*)d_in[0];
    const void*  eidx  = d_in[1];
    const void*  batch = d_in[2];
    const float* W1 = (const float*)d_in[3];
    const float* b1 = (const float*)d_in[4];
    const float* W2 = (const float*)d_in[5];
    const float* b2 = (const float*)d_in[6];
    const float* W3 = (const float*)d_in[7];
    const float* b3 = (const float*)d_in[8];
    const float* Wlin = (const float*)d_in[9];
    const float* blin = (const float*)d_in[10];
    float* out = (float*)d_out;

    int N = in_sizes[0] / DIM;
    int E = in_sizes[1] / 2;

    uint4* p8;
    __half *bufA, *x16, *W16;
    cudaGetSymbolAddress((void**)&p8, g_p8);
    cudaGetSymbolAddress((void**)&bufA, g_bufA);
    cudaGetSymbolAddress((void**)&x16, g_x16);
    cudaGetSymbolAddress((void**)&W16, g_W16);
    const uint8_t* p8b = (const uint8_t*)p8;

    static cudaStream_t s2 = nullptr;
    static cudaEvent_t evFork = nullptr, evScan = nullptr, evJoin = nullptr;
    if (!s2) {
        cudaStreamCreateWithFlags(&s2, cudaStreamNonBlocking);
        cudaEventCreateWithFlags(&evFork, cudaEventDisableTiming);
        cudaEventCreateWithFlags(&evScan, cudaEventDisableTiming);
        cudaEventCreateWithFlags(&evJoin, cudaEventDisableTiming);
    }

    int nbScan = (N + 1023) / 1024;
    int gemmBlocks = (N + 63) / 64;
    int aggBlocks = (N * 32 + 255) / 256;

    // side stream: prep, then gemm1 once dinv is ready
    cudaEventRecord(evFork, 0);
    cudaStreamWaitEvent(s2, evFork, 0);
    prep_kernel<<<(N * 16 + 255) / 256, 256, 0, s2>>>(x, W1, W2, W3, N * 16);

    // main: edge setup chain
    deg_kernel<<<(E + 255) / 256, 256>>>(eidx, E, N);
    scan_kernel<<<nbScan, 256>>>(N, E);
    cudaEventRecord(evScan, 0);

    // gemm1 overlaps scatter
    cudaStreamWaitEvent(s2, evScan, 0);
    gemm_mma_kernel<<<gemmBlocks, 256, 0, s2>>>(x16, W16, p8, N);
    cudaEventRecord(evJoin, s2);

    scatter_kernel<<<(E + 255) / 256, 256>>>(eidx, E, N);
    cudaStreamWaitEvent(0, evJoin, 0);

    // layers
    aggregate_kernel<<<aggBlocks, 256>>>(p8b, bufA, b1, 1, N);
    gemm_mma_kernel<<<gemmBlocks, 256>>>(bufA, W16 + 4096, p8, N);
    aggregate_kernel<<<aggBlocks, 256>>>(p8b, bufA, b2, 1, N);
    gemm_mma_kernel<<<gemmBlocks, 256>>>(bufA, W16 + 8192, p8, N);
    aggregate_kernel<<<aggBlocks, 256>>>(p8b, bufA, b3, 0, N);

    poolfinal_kernel<<<GRAPHS, 256>>>(bufA, batch, Wlin, blin, out, N);
}

// round 14
// speedup vs baseline: 1.1071x; 1.0589x over previous
#include <cuda_runtime.h>
#include <cuda_fp16.h>
#include <cuda_fp8.h>
#include <cstdint>

// ---------------- Problem constants / scratch ----------------
#define MAXN 131072
#define MAXE 2000000
#define GRAPHS 128
#define DIM 64

__device__ int       g_is64;
__device__ int       g_indeg[MAXN];
__device__ float     g_dinv[MAXN];
__device__ int       g_rowptr[MAXN + 1];
__device__ int       g_cursor[MAXN];
__device__ long long g_look[192];
__device__ int       g_esrc[MAXE];          // edge = src only (4 B)
__device__ uint4     g_p8[MAXN * 4];        // fp8 payload p = dinv * xw
__device__ __half    g_x16[MAXN * DIM];     // fp16 copy of input features
__device__ __half    g_bufA[MAXN * DIM];    // fp16 hidden (single buffer, reused)
__device__ __half    g_W16[3 * DIM * DIM];

// ---------------- helpers ----------------
__device__ __forceinline__ int loadIdx(const void* p, long long i) {
    if (g_is64) return (int)((const long long*)p)[i];
    return ((const int*)p)[i];
}

__device__ __forceinline__ int detect64(const void* p, int n) {
    const long long* q = (const long long*)p;
    long long v = q[threadIdx.x & 31];
    unsigned ok = __ballot_sync(0xffffffffu, v >= 0 && v < (long long)n);
    return ok == 0xffffffffu;
}

// ---------------- prep (side stream): x fp32->fp16, W fp32->fp16 ----------------
__global__ void prep_kernel(const float* __restrict__ x, const float* __restrict__ W1,
                            const float* __restrict__ W2, const float* __restrict__ W3,
                            int n4) {
    int gid = blockIdx.x * blockDim.x + threadIdx.x;
    if (gid < 3072) {
        const float* Ws = (gid < 1024) ? W1 : (gid < 2048 ? W2 : W3);
        int j = gid & 1023;
        float4 v = ((const float4*)Ws)[j];
        __half2 p0 = __floats2half2_rn(v.x, v.y);
        __half2 p1 = __floats2half2_rn(v.z, v.w);
        uint2 u;
        u.x = *(unsigned*)&p0;
        u.y = *(unsigned*)&p1;
        *(uint2*)&g_W16[(gid >> 10) * 4096 + j * 4] = u;
    }
    for (int i = gid; i < n4; i += gridDim.x * blockDim.x) {
        float4 v = ((const float4*)x)[i];
        __half2 p0 = __floats2half2_rn(v.x, v.y);
        __half2 p1 = __floats2half2_rn(v.z, v.w);
        uint2 u;
        u.x = *(unsigned*)&p0;
        u.y = *(unsigned*)&p1;
        ((uint2*)g_x16)[i] = u;
    }
}

// ---------------- degree histogram: 4 edges/thread, 16 B vector index loads ----------------
__global__ void deg_kernel(const void* eidx, int E, int n) {
    int is64 = detect64(eidx, n);
    if (blockIdx.x == 0 && threadIdx.x == 0) g_is64 = is64;
    int base = (blockIdx.x * blockDim.x + threadIdx.x) * 4;
    if (base >= E) return;
    if (base + 3 < E) {
        int d0, d1, d2, d3;
        if (is64) {
            const longlong2* q = (const longlong2*)((const long long*)eidx + E);
            longlong2 a = q[base >> 1];
            longlong2 b = q[(base >> 1) + 1];
            d0 = (int)a.x; d1 = (int)a.y; d2 = (int)b.x; d3 = (int)b.y;
        } else {
            int4 a = *(const int4*)((const int*)eidx + E + base);
            d0 = a.x; d1 = a.y; d2 = a.z; d3 = a.w;
        }
        atomicAdd(&g_indeg[d0], 1);
        atomicAdd(&g_indeg[d1], 1);
        atomicAdd(&g_indeg[d2], 1);
        atomicAdd(&g_indeg[d3], 1);
    } else {
        for (int e = base; e < E; e++) {
            int d = is64 ? (int)((const long long*)eidx)[(long long)E + e]
                         : ((const int*)eidx)[E + e];
            atomicAdd(&g_indeg[d], 1);
        }
    }
}

// ---------------- single-kernel scan with decoupled lookback ----------------
__global__ void scan_kernel(int n, int E) {
    __shared__ int sh[256];
    __shared__ int s_off;
    int bid = blockIdx.x, tid = threadIdx.x;
    int base = bid * 1024 + tid * 4;
    int v[4];
#pragma unroll
    for (int i = 0; i < 4; i++) {
        int idx = base + i;
        v[i] = (idx < n) ? g_indeg[idx] : 0;
        if (idx < n) {
            g_dinv[idx] = rsqrtf((float)(v[i] + 1));  // +1 self-loop
            g_indeg[idx] = 0;                          // re-arm for next launch
        }
    }
    int tsum = v[0] + v[1] + v[2] + v[3];
    sh[tid] = tsum;
    __syncthreads();
    int val = tsum;
    for (int off = 1; off < 256; off <<= 1) {
        int t = (tid >= off) ? sh[tid - off] : 0;
        __syncthreads();
        val += t;
        sh[tid] = val;
        __syncthreads();
    }
    if (tid == 255)
        ((volatile long long*)g_look)[bid] = 0x100000000LL | (unsigned)val;
    int myExcl = val - tsum;
    if (tid < 32) {
        int off = 0;
        for (int j = tid; j < bid; j += 32) {
            long long lv;
            do { lv = ((volatile long long*)g_look)[j]; } while (lv == 0);
            off += (int)(lv & 0xffffffffLL);
        }
#pragma unroll
        for (int s = 16; s > 0; s >>= 1) off += __shfl_down_sync(0xffffffffu, off, s);
        if (tid == 0) s_off = off;
    }
    __syncthreads();
    int run = myExcl + s_off;
#pragma unroll
    for (int i = 0; i < 4; i++) {
        int idx = base + i;
        if (idx < n) {
            g_rowptr[idx] = run;
            g_cursor[idx] = run;
        }
        run += v[i];
    }
    if (bid == 0 && tid == 0) g_rowptr[n] = E;
}

// ---------------- edge scatter: 4 edges/thread, 16 B vector index loads ----------------
__global__ void scatter_kernel(const void* eidx, int E, int n) {
    if (blockIdx.x == 0 && threadIdx.x < 192) g_look[threadIdx.x] = 0;
    int is64 = detect64(eidx, n);
    int base = (blockIdx.x * blockDim.x + threadIdx.x) * 4;
    if (base >= E) return;
    if (base + 3 < E) {
        int s0, s1, s2, s3, d0, d1, d2, d3;
        if (is64) {
            const longlong2* qs = (const longlong2*)((const long long*)eidx);
            const longlong2* qd = (const longlong2*)((const long long*)eidx + E);
            longlong2 sa = qs[base >> 1];
            longlong2 sb = qs[(base >> 1) + 1];
            longlong2 da = qd[base >> 1];
            longlong2 db = qd[(base >> 1) + 1];
            s0 = (int)sa.x; s1 = (int)sa.y; s2 = (int)sb.x; s3 = (int)sb.y;
            d0 = (int)da.x; d1 = (int)da.y; d2 = (int)db.x; d3 = (int)db.y;
        } else {
            int4 sa = *(const int4*)((const int*)eidx + base);
            int4 da = *(const int4*)((const int*)eidx + E + base);
            s0 = sa.x; s1 = sa.y; s2 = sa.z; s3 = sa.w;
            d0 = da.x; d1 = da.y; d2 = da.z; d3 = da.w;
        }
        int p0 = atomicAdd(&g_cursor[d0], 1);
        int p1 = atomicAdd(&g_cursor[d1], 1);
        int p2 = atomicAdd(&g_cursor[d2], 1);
        int p3 = atomicAdd(&g_cursor[d3], 1);
        g_esrc[p0] = s0;
        g_esrc[p1] = s1;
        g_esrc[p2] = s2;
        g_esrc[p3] = s3;
    } else {
        for (int e = base; e < E; e++) {
            int s, d;
            if (is64) {
                s = (int)((const long long*)eidx)[e];
                d = (int)((const long long*)eidx)[(long long)E + e];
            } else {
                s = ((const int*)eidx)[e];
                d = ((const int*)eidx)[E + e];
            }
            int pos = atomicAdd(&g_cursor[d], 1);
            g_esrc[pos] = s;
        }
    }
}

// ---------------- tensor-core GEMM: P[n,64](fp8) = dinv[row] * (X[n,64] @ W) ----------------
__global__ __launch_bounds__(256) void gemm_mma_kernel(
    const __half* __restrict__ X, const __half* __restrict__ Wg,
    uint4* __restrict__ P, int n) {
    __shared__ __half Wh[64 * 72];
    __shared__ __half Xsh[64 * 72];
    __shared__ float dsh[64];
    __shared__ __align__(16) uint8_t Ysh[64 * 64];
    int tid = threadIdx.x;
    int warp = tid >> 5, lane = tid & 31;
    int nb = blockIdx.x * 64;

    // 1) cp.async prefetch X rows
#pragma unroll
    for (int i = 0; i < 4; i++) {
        int idx = i * 256 + tid;           // 0..1023
        int row = idx >> 4, seg = idx & 15;
        __half* dst = &Xsh[row * 72 + seg * 4];
        if (nb + row < n) {
            const __half* src = X + (size_t)(nb + row) * 64 + seg * 4;
            uint32_t sdst = (uint32_t)__cvta_generic_to_shared(dst);
            asm volatile("cp.async.ca.shared.global [%0], [%1], 8;" :: "r"(sdst), "l"(src));
        } else {
            *(uint2*)dst = make_uint2(0, 0);
        }
    }
    asm volatile("cp.async.commit_group;");

    // 2) W fp16 -> smem (k-major, stride 72)
    for (int i = tid; i < 512; i += 256) {
        uint4 u = ((const uint4*)Wg)[i];  // 8 halfs
        int k = i >> 3, c = (i & 7) * 8;
        *(uint4*)&Wh[k * 72 + c] = u;
    }
    if (tid < 64) dsh[tid] = (nb + tid < n) ? g_dinv[nb + tid] : 0.f;

    asm volatile("cp.async.wait_group 0;");
    __syncthreads();

    int rt = warp >> 1;
    int ch = warp & 1;
    int r0 = rt * 16;
    float D[4][4];
#pragma unroll
    for (int nc = 0; nc < 4; nc++)
#pragma unroll
        for (int j = 0; j < 4; j++) D[nc][j] = 0.f;

#pragma unroll
    for (int kc = 0; kc < 4; kc++) {
        uint32_t A[4];
        {
            const __half* ap = &Xsh[(r0 + (lane & 15)) * 72 + kc * 16 + (lane >> 4) * 8];
            uint32_t sa = (uint32_t)__cvta_generic_to_shared(ap);
            asm volatile("ldmatrix.sync.aligned.m8n8.x4.shared.b16 {%0,%1,%2,%3}, [%4];"
                         : "=r"(A[0]), "=r"(A[1]), "=r"(A[2]), "=r"(A[3]) : "r"(sa));
        }
        uint32_t B[4][2];
#pragma unroll
        for (int np = 0; np < 2; np++) {
            int krow = kc * 16 + (lane & 15);
            int ncol = ch * 32 + np * 16 + (lane >> 4) * 8;
            const __half* bp = &Wh[krow * 72 + ncol];
            uint32_t sb = (uint32_t)__cvta_generic_to_shared(bp);
            asm volatile("ldmatrix.sync.aligned.m8n8.x4.trans.shared.b16 {%0,%1,%2,%3}, [%4];"
                         : "=r"(B[np * 2][0]), "=r"(B[np * 2][1]),
                           "=r"(B[np * 2 + 1][0]), "=r"(B[np * 2 + 1][1])
                         : "r"(sb));
        }
#pragma unroll
        for (int nc = 0; nc < 4; nc++) {
            asm volatile(
                "mma.sync.aligned.m16n8k16.row.col.f32.f16.f16.f32 "
                "{%0,%1,%2,%3}, {%4,%5,%6,%7}, {%8,%9}, {%0,%1,%2,%3};"
                : "+f"(D[nc][0]), "+f"(D[nc][1]), "+f"(D[nc][2]), "+f"(D[nc][3])
                : "r"(A[0]), "r"(A[1]), "r"(A[2]), "r"(A[3]),
                  "r"(B[nc][0]), "r"(B[nc][1]));
        }
    }
    int g = lane >> 2;
    int cb = 2 * (lane & 3);
    float dlo = dsh[r0 + g];
    float dhi = dsh[r0 + g + 8];
#pragma unroll
    for (int nc = 0; nc < 4; nc++) {
        int c0 = ch * 32 + nc * 8 + cb;
        float2 lo = make_float2(D[nc][0] * dlo, D[nc][1] * dlo);
        float2 hi = make_float2(D[nc][2] * dhi, D[nc][3] * dhi);
        unsigned short p0 = __nv_cvt_float2_to_fp8x2(lo, __NV_SATFINITE, __NV_E4M3);
        unsigned short p1 = __nv_cvt_float2_to_fp8x2(hi, __NV_SATFINITE, __NV_E4M3);
        *(unsigned short*)&Ysh[(r0 + g) * 64 + c0] = p0;
        *(unsigned short*)&Ysh[(r0 + g + 8) * 64 + c0] = p1;
    }
    __syncthreads();
    {
        int row = tid >> 2, q = tid & 3;
        int node = nb + row;
        if (node < n)
            P[(size_t)node * 4 + q] = ((const uint4*)Ysh)[row * 4 + q];
    }
}

// ---------------- aggregation: out = dinv[dst]*(sum p[src] + p[self]) + b ----------------
// Exact R9 shape: 16 lanes x 4 B per row, 8-deep pipeline, serial 2-wide remainder.
__device__ __forceinline__ float4 fp8quad(const uint8_t* base, int node, int li) {
    uint32_t u = *(const uint32_t*)(base + (size_t)node * 64 + li * 4);
    __half2_raw h0 = __nv_cvt_fp8x2_to_halfraw2((unsigned short)(u & 0xffff), __NV_E4M3);
    __half2_raw h1 = __nv_cvt_fp8x2_to_halfraw2((unsigned short)(u >> 16), __NV_E4M3);
    float2 a = __half22float2(*(__half2*)&h0);
    float2 b = __half22float2(*(__half2*)&h1);
    return make_float4(a.x, a.y, b.x, b.y);
}

__global__ void aggregate_kernel(const uint8_t* __restrict__ p8, __half* __restrict__ out,
                                 const float* __restrict__ bias, int relu, int n) {
    int node = (blockIdx.x * blockDim.x + threadIdx.x) >> 5;
    int lane = threadIdx.x & 31;
    if (node >= n) return;
    int start = g_rowptr[node];
    int end = g_rowptr[node + 1];
    float dv = g_dinv[node];
    int li = lane & 15;
    int half_ = lane >> 4;
    float4 acc = make_float4(0.f, 0.f, 0.f, 0.f);
    if (half_ == 0) acc = fp8quad(p8, node, li);  // self contribution once
    int e = start + half_;
    // 8-deep pipeline (16 edges per warp iteration)
    for (; e + 14 < end; e += 16) {
        int s[8];
#pragma unroll
        for (int i = 0; i < 8; i++) s[i] = g_esrc[e + 2 * i];
        float4 v[8];
#pragma unroll
        for (int i = 0; i < 8; i++) v[i] = fp8quad(p8, s[i], li);
#pragma unroll
        for (int i = 0; i < 8; i++) {
            acc.x += v[i].x; acc.y += v[i].y;
            acc.z += v[i].z; acc.w += v[i].w;
        }
    }
    for (; e < end; e += 2) {
        float4 v = fp8quad(p8, g_esrc[e], li);
        acc.x += v.x; acc.y += v.y;
        acc.z += v.z; acc.w += v.w;
    }
    // combine halves -> lanes 0..15 hold dims [4*li, 4*li+4)
    acc.x += __shfl_down_sync(0xffffffffu, acc.x, 16);
    acc.y += __shfl_down_sync(0xffffffffu, acc.y, 16);
    acc.z += __shfl_down_sync(0xffffffffu, acc.z, 16);
    acc.w += __shfl_down_sync(0xffffffffu, acc.w, 16);
    if (lane < 16) {
        float4 b4 = *(const float4*)(bias + li * 4);
        float o0 = dv * acc.x + b4.x;
        float o1 = dv * acc.y + b4.y;
        float o2 = dv * acc.z + b4.z;
        float o3 = dv * acc.w + b4.w;
        if (relu) {
            o0 = fmaxf(o0, 0.f); o1 = fmaxf(o1, 0.f);
            o2 = fmaxf(o2, 0.f); o3 = fmaxf(o3, 0.f);
        }
        __half2 p0 = __floats2half2_rn(o0, o1);
        __half2 p1 = __floats2half2_rn(o2, o3);
        uint2 u;
        u.x = *(unsigned*)&p0;
        u.y = *(unsigned*)&p1;
        ((uint2*)out)[(size_t)node * 16 + li] = u;
    }
}

// ---------------- fused pool + linear (batch sorted -> contiguous ranges) ----------------
__device__ __forceinline__ int lower_bound_batch(const void* batch, int n, int key) {
    int lo = 0, hi = n;
    while (lo < hi) {
        int mid = (lo + hi) >> 1;
        if (loadIdx(batch, mid) < key) lo = mid + 1;
        else hi = mid;
    }
    return lo;
}

__global__ void poolfinal_kernel(const __half* __restrict__ h, const void* batch,
                                 const float* __restrict__ Wlin, const float* __restrict__ blin,
                                 float* __restrict__ out, int n) {
    int g = blockIdx.x;
    int tid = threadIdx.x;  // 256
    __shared__ int s_lo, s_hi;
    if (tid == 0) s_lo = lower_bound_batch(batch, n, g);
    if (tid == 1) s_hi = lower_bound_batch(batch, n, g + 1);
    __syncthreads();
    int lo = s_lo, hi = s_hi;
    int dim = tid & 63;
    int sub = tid >> 6;
    float acc = 0.f;
    for (int node = lo + sub; node < hi; node += 4)
        acc += __half2float(h[(size_t)node * 64 + dim]);
    __shared__ float red[256];
    __shared__ float mean[64];
    red[tid] = acc;
    __syncthreads();
    if (tid < 64) {
        float s = red[tid] + red[tid + 64] + red[tid + 128] + red[tid + 192];
        float cnt = (float)(hi - lo);
        mean[tid] = s / fmaxf(cnt, 1.0f);
    }
    __syncthreads();
    if (tid < 64) {
        float a = blin[tid];
#pragma unroll
        for (int k = 0; k < 64; k++) a += mean[k] * Wlin[k * 64 + tid];
        out[g * 64 + tid] = a;
    }
}

// ---------------- launch ----------------
extern "C" void kernel_launch(void* const* d_in, const int* in_sizes, int n_in,
                              void* d_out, int out_size) {
    const float* x     = (const float*)d_in[0];
    const void*  eidx  = d_in[1];
    const void*  batch = d_in[2];
    const float* W1 = (const float*)d_in[3];
    const float* b1 = (const float*)d_in[4];
    const float* W2 = (const float*)d_in[5];
    const float* b2 = (const float*)d_in[6];
    const float* W3 = (const float*)d_in[7];
    const float* b3 = (const float*)d_in[8];
    const float* Wlin = (const float*)d_in[9];
    const float* blin = (const float*)d_in[10];
    float* out = (float*)d_out;

    int N = in_sizes[0] / DIM;
    int E = in_sizes[1] / 2;

    uint4* p8;
    __half *bufA, *x16, *W16;
    cudaGetSymbolAddress((void**)&p8, g_p8);
    cudaGetSymbolAddress((void**)&bufA, g_bufA);
    cudaGetSymbolAddress((void**)&x16, g_x16);
    cudaGetSymbolAddress((void**)&W16, g_W16);
    const uint8_t* p8b = (const uint8_t*)p8;

    static cudaStream_t s2 = nullptr;
    static cudaEvent_t evFork = nullptr, evScan = nullptr, evJoin = nullptr;
    if (!s2) {
        cudaStreamCreateWithFlags(&s2, cudaStreamNonBlocking);
        cudaEventCreateWithFlags(&evFork, cudaEventDisableTiming);
        cudaEventCreateWithFlags(&evScan, cudaEventDisableTiming);
        cudaEventCreateWithFlags(&evJoin, cudaEventDisableTiming);
    }

    int nbScan = (N + 1023) / 1024;
    int gemmBlocks = (N + 63) / 64;
    int aggBlocks = (N * 32 + 255) / 256;
    int edgeBlocks4 = (E / 4 + 256) / 256;

    // side stream: prep, then gemm1 once dinv is ready
    cudaEventRecord(evFork, 0);
    cudaStreamWaitEvent(s2, evFork, 0);
    prep_kernel<<<(N * 16 + 255) / 256, 256, 0, s2>>>(x, W1, W2, W3, N * 16);

    // main: edge setup chain
    deg_kernel<<<edgeBlocks4, 256>>>(eidx, E, N);
    scan_kernel<<<nbScan, 256>>>(N, E);
    cudaEventRecord(evScan, 0);

    // gemm1 overlaps scatter
    cudaStreamWaitEvent(s2, evScan, 0);
    gemm_mma_kernel<<<gemmBlocks, 256, 0, s2>>>(x16, W16, p8, N);
    cudaEventRecord(evJoin, s2);

    scatter_kernel<<<edgeBlocks4, 256>>>(eidx, E, N);
    cudaStreamWaitEvent(0, evJoin, 0);

    // layers
    aggregate_kernel<<<aggBlocks, 256>>>(p8b, bufA, b1, 1, N);
    gemm_mma_kernel<<<gemmBlocks, 256>>>(bufA, W16 + 4096, p8, N);
    aggregate_kernel<<<aggBlocks, 256>>>(p8b, bufA, b2, 1, N);
    gemm_mma_kernel<<<gemmBlocks, 256>>>(bufA, W16 + 8192, p8, N);
    aggregate_kernel<<<aggBlocks, 256>>>(p8b, bufA, b3, 0, N);

    poolfinal_kernel<<<GRAPHS, 256>>>(bufA, batch, Wlin, blin, out, N);
}